// round 11
// baseline (speedup 1.0000x reference)
#include <cuda_runtime.h>

#define N_NODES 50000
#define N_EDGES 800000
#define D 96
#define WS 100                  // padded weight stride (floats)
#define SCAN_T 1024
#define SCAN_B ((N_NODES + SCAN_T - 1) / SCAN_T)   // 49

typedef unsigned long long u64;

__device__ __align__(16) float g_agg[N_NODES * D];   // gathered mean features
__device__ __align__(16) float g_h[N_NODES * D];     // layer-1 activations
__device__ int g_deg[N_NODES];
__device__ int g_off[N_NODES + 1];
__device__ int g_cur[N_NODES];                        // placement cursors (seeded)
__device__ int g_src[N_EDGES];                        // CSR: src ids grouped by dst
__device__ int g_part[SCAN_B];
__device__ int g_flag[SCAN_B];
__device__ int g_is64;

__device__ __forceinline__ u64 pack2(float lo, float hi) {
    u64 r; asm("mov.b64 %0, {%1, %2};" : "=l"(r) : "f"(lo), "f"(hi)); return r;
}
__device__ __forceinline__ void unpack2(u64 v, float& lo, float& hi) {
    asm("mov.b64 {%0, %1}, %2;" : "=f"(lo), "=f"(hi) : "l"(v));
}
__device__ __forceinline__ void fma2(u64& d, u64 a, u64 b) {
    asm("fma.rn.f32x2 %0, %1, %2, %0;" : "+l"(d) : "l"(a), "l"(b));
}
__device__ __forceinline__ int clampi(int v) {
    return min(max(v, 0), N_NODES - 1);
}

// ---------------------------------------------------------------------------
// Zero degrees + flags; block 0 detects edge_index element width.
// ---------------------------------------------------------------------------
__global__ void zero_detect_kernel(const int* __restrict__ w) {
    int i = blockIdx.x * blockDim.x + threadIdx.x;
    if (i < N_NODES) g_deg[i] = 0;
    if (i < SCAN_B) g_flag[i] = 0;
    if (blockIdx.x == 0 && threadIdx.x < 64) {
        int t = threadIdx.x;
        int bad = (w[2 * t + 1] != 0) ? 1 : 0;
        unsigned m0 = __ballot_sync(0xffffffffu, bad);
        __shared__ unsigned s[2];
        s[t >> 5] = m0;
        __syncwarp();
        if (t == 0) {
            __threadfence_block();
            g_is64 = (s[0] | s[1]) ? 0 : 1;
        }
    }
}

__device__ __forceinline__ int load_idx(const void* eiv, int pos) {
    int v;
    if (g_is64) v = (int)((const long long*)eiv)[pos];
    else        v = ((const int*)eiv)[pos];
    return clampi(v);
}

// hist: 4 edges per thread, vector index loads
__global__ void hist_kernel(const void* __restrict__ eiv) {
    int e = 4 * (blockIdx.x * blockDim.x + threadIdx.x);
    if (e + 3 < N_EDGES) {
        int d0, d1, d2, d3;
        if (g_is64) {
            const longlong2* p = (const longlong2*)((const long long*)eiv + N_EDGES + e);
            longlong2 a = p[0], b = p[1];
            d0 = (int)a.x; d1 = (int)a.y; d2 = (int)b.x; d3 = (int)b.y;
        } else {
            int4 a = *(const int4*)((const int*)eiv + N_EDGES + e);
            d0 = a.x; d1 = a.y; d2 = a.z; d3 = a.w;
        }
        atomicAdd(&g_deg[clampi(d0)], 1);
        atomicAdd(&g_deg[clampi(d1)], 1);
        atomicAdd(&g_deg[clampi(d2)], 1);
        atomicAdd(&g_deg[clampi(d3)], 1);
    } else {
        for (int k = e; k < N_EDGES; k++)
            atomicAdd(&g_deg[load_idx(eiv, N_EDGES + k)], 1);
    }
}

// ---------------------------------------------------------------------------
// Single-pass scan with decoupled lookback; seeds g_cur with offsets.
// ---------------------------------------------------------------------------
__global__ __launch_bounds__(SCAN_T) void scan_kernel() {
    __shared__ int wsum[32];
    __shared__ int red[2];
    __shared__ int sbase;

    int tid = threadIdx.x;
    int bx  = blockIdx.x;
    int i = bx * SCAN_T + tid;
    int v = (i < N_NODES) ? g_deg[i] : 0;

    int s = v;
#pragma unroll
    for (int o = 1; o < 32; o <<= 1) {
        int u = __shfl_up_sync(0xffffffffu, s, o);
        if ((tid & 31) >= o) s += u;
    }
    if ((tid & 31) == 31) wsum[tid >> 5] = s;
    __syncthreads();
    if (tid < 32) {
        int t = wsum[tid];
#pragma unroll
        for (int o = 1; o < 32; o <<= 1) {
            int u = __shfl_up_sync(0xffffffffu, t, o);
            if (tid >= o) t += u;
        }
        wsum[tid] = t;
    }
    __syncthreads();

    if (tid == 0) {
        g_part[bx] = wsum[31];
        __threadfence();
        ((volatile int*)g_flag)[bx] = 1;
    }

    if (tid < 64) {
        int val = 0;
        if (tid < bx) {
            while (((volatile int*)g_flag)[tid] == 0) {}
            __threadfence();
            val = ((volatile int*)g_part)[tid];
        }
#pragma unroll
        for (int o = 16; o > 0; o >>= 1)
            val += __shfl_xor_sync(0xffffffffu, val, o);
        if ((tid & 31) == 0) red[tid >> 5] = val;
    }
    __syncthreads();
    if (tid == 0) sbase = red[0] + red[1];
    __syncthreads();

    int warp = tid >> 5;
    int wbase = warp ? wsum[warp - 1] : 0;
    int excl = sbase + wbase + (s - v);
    if (i < N_NODES) {
        g_off[i] = excl;
        g_cur[i] = excl;
        if (i == N_NODES - 1) g_off[N_NODES] = excl + v;
    }
}

// place: 2 edges per thread, paired index loads; atomic on seeded cursor
__global__ void place_kernel(const void* __restrict__ eiv) {
    int e = 2 * (blockIdx.x * blockDim.x + threadIdx.x);
    if (e + 1 < N_EDGES) {
        int s0, s1, d0, d1;
        if (g_is64) {
            longlong2 sp = *(const longlong2*)((const long long*)eiv + e);
            longlong2 dp = *(const longlong2*)((const long long*)eiv + N_EDGES + e);
            s0 = (int)sp.x; s1 = (int)sp.y; d0 = (int)dp.x; d1 = (int)dp.y;
        } else {
            int2 sp = *(const int2*)((const int*)eiv + e);
            int2 dp = *(const int2*)((const int*)eiv + N_EDGES + e);
            s0 = sp.x; s1 = sp.y; d0 = dp.x; d1 = dp.y;
        }
        s0 = clampi(s0); s1 = clampi(s1);
        int p0 = atomicAdd(&g_cur[clampi(d0)], 1);
        int p1 = atomicAdd(&g_cur[clampi(d1)], 1);
        if (p0 >= 0 && p0 < N_EDGES) g_src[p0] = s0;
        if (p1 >= 0 && p1 < N_EDGES) g_src[p1] = s1;
    } else if (e < N_EDGES) {
        int src = load_idx(eiv, e);
        int dst = load_idx(eiv, N_EDGES + e);
        int pos = atomicAdd(&g_cur[dst], 1);
        if (pos >= 0 && pos < N_EDGES) g_src[pos] = src;
    }
}

// ---------------------------------------------------------------------------
// Gather mean: one warp per node; 24 active lanes, one float4 per lane per
// edge. 8-edge unroll to hide L2 latency.
// ---------------------------------------------------------------------------
__global__ __launch_bounds__(256) void gather_kernel(const float* __restrict__ x,
                                                     int from_h) {
    int warp = (blockIdx.x * blockDim.x + threadIdx.x) >> 5;
    int lane = threadIdx.x & 31;
    if (warp >= N_NODES) return;
    const float* feat = from_h ? (const float*)g_h : x;
    int beg = g_off[warp];
    int end = g_off[warp + 1];
    bool act = lane < 24;
    float4 a = make_float4(0.f, 0.f, 0.f, 0.f);
    float4 b = make_float4(0.f, 0.f, 0.f, 0.f);
    int i = beg;
    for (; i + 7 < end; i += 8) {
        int s0 = g_src[i],     s1 = g_src[i + 1], s2 = g_src[i + 2], s3 = g_src[i + 3];
        int s4 = g_src[i + 4], s5 = g_src[i + 5], s6 = g_src[i + 6], s7 = g_src[i + 7];
        if (act) {
            float4 v0 = ((const float4*)(feat + (size_t)s0 * D))[lane];
            float4 v1 = ((const float4*)(feat + (size_t)s1 * D))[lane];
            float4 v2 = ((const float4*)(feat + (size_t)s2 * D))[lane];
            float4 v3 = ((const float4*)(feat + (size_t)s3 * D))[lane];
            float4 v4 = ((const float4*)(feat + (size_t)s4 * D))[lane];
            float4 v5 = ((const float4*)(feat + (size_t)s5 * D))[lane];
            float4 v6 = ((const float4*)(feat + (size_t)s6 * D))[lane];
            float4 v7 = ((const float4*)(feat + (size_t)s7 * D))[lane];
            a.x += (v0.x + v1.x) + (v2.x + v3.x);
            a.y += (v0.y + v1.y) + (v2.y + v3.y);
            a.z += (v0.z + v1.z) + (v2.z + v3.z);
            a.w += (v0.w + v1.w) + (v2.w + v3.w);
            b.x += (v4.x + v5.x) + (v6.x + v7.x);
            b.y += (v4.y + v5.y) + (v6.y + v7.y);
            b.z += (v4.z + v5.z) + (v6.z + v7.z);
            b.w += (v4.w + v5.w) + (v6.w + v7.w);
        }
    }
    for (; i + 1 < end; i += 2) {
        int s0 = g_src[i], s1 = g_src[i + 1];
        if (act) {
            float4 v0 = ((const float4*)(feat + (size_t)s0 * D))[lane];
            float4 v1 = ((const float4*)(feat + (size_t)s1 * D))[lane];
            a.x += v0.x + v1.x; a.y += v0.y + v1.y;
            a.z += v0.z + v1.z; a.w += v0.w + v1.w;
        }
    }
    if (i < end) {
        int s0 = g_src[i];
        if (act) {
            float4 v0 = ((const float4*)(feat + (size_t)s0 * D))[lane];
            a.x += v0.x; a.y += v0.y; a.z += v0.z; a.w += v0.w;
        }
    }
    if (act) {
        float inv = 1.0f / (float)max(end - beg, 1);
        float4 r;
        r.x = (a.x + b.x) * inv;
        r.y = (a.y + b.y) * inv;
        r.z = (a.z + b.z) * inv;
        r.w = (a.w + b.w) * inv;
        ((float4*)(g_agg + (size_t)warp * D))[lane] = r;
    }
}

// ---------------------------------------------------------------------------
// Fused SAGE linear layer, 4 threads per node (24 outputs each), 128-thread
// blocks (32 nodes) -> half-size blocks kill the 2-wave quantization penalty.
// No min-blocks reg cap (R8's mistake): ~60 regs, no spills.
// Per-warp LDS addresses: 4 distinct banksets (obase 0/96/192/288 B) ->
// conflict-free broadcast.
// ---------------------------------------------------------------------------
__global__ __launch_bounds__(128) void gemm_kernel(
    const float* __restrict__ x, int in_h,
    const float* __restrict__ Wl,
    const float* __restrict__ Wr,
    const float* __restrict__ bias,
    float* __restrict__ out, int out_h,
    int apply_elu)
{
    __shared__ __align__(16) float ws[D * WS];   // ws[k*WS + o] = W[o][k]
    __shared__ float bsm[D];

    const float* feat = in_h ? (const float*)g_h : x;
    float* dst = out_h ? (float*)g_h : out;

    for (int i = threadIdx.x; i < D * D; i += 128) {
        int o = i / D, k = i % D;
        ws[k * WS + o] = Wl[i];
    }
    if (threadIdx.x < D) bsm[threadIdx.x] = bias[threadIdx.x];
    __syncthreads();

    int node = blockIdx.x * 32 + (threadIdx.x >> 2);
    int obase = (threadIdx.x & 3) * 24;          // this thread's output quarter
    bool active = node < N_NODES;

    u64 acc[12];
#pragma unroll
    for (int j = 0; j < 12; j++)
        acc[j] = pack2(bsm[obase + 2 * j], bsm[obase + 2 * j + 1]);

    const float4* a4 = (const float4*)(g_agg + (size_t)node * D);
    const float4* f4 = (const float4*)(feat + (size_t)node * D);

    if (active) {
#pragma unroll 1
        for (int kb = 0; kb < D / 4; kb++) {
            float4 av = a4[kb];
            const ulonglong2* w0 = (const ulonglong2*)(ws + (4 * kb + 0) * WS + obase);
            const ulonglong2* w1 = (const ulonglong2*)(ws + (4 * kb + 1) * WS + obase);
            const ulonglong2* w2 = (const ulonglong2*)(ws + (4 * kb + 2) * WS + obase);
            const ulonglong2* w3 = (const ulonglong2*)(ws + (4 * kb + 3) * WS + obase);
            u64 ax = pack2(av.x, av.x);
            u64 ay = pack2(av.y, av.y);
            u64 az = pack2(av.z, av.z);
            u64 aw = pack2(av.w, av.w);
#pragma unroll
            for (int j = 0; j < 6; j++) {
                ulonglong2 w = w0[j];
                fma2(acc[2 * j], ax, w.x); fma2(acc[2 * j + 1], ax, w.y);
            }
#pragma unroll
            for (int j = 0; j < 6; j++) {
                ulonglong2 w = w1[j];
                fma2(acc[2 * j], ay, w.x); fma2(acc[2 * j + 1], ay, w.y);
            }
#pragma unroll
            for (int j = 0; j < 6; j++) {
                ulonglong2 w = w2[j];
                fma2(acc[2 * j], az, w.x); fma2(acc[2 * j + 1], az, w.y);
            }
#pragma unroll
            for (int j = 0; j < 6; j++) {
                ulonglong2 w = w3[j];
                fma2(acc[2 * j], aw, w.x); fma2(acc[2 * j + 1], aw, w.y);
            }
        }
    }

    __syncthreads();
    for (int i = threadIdx.x; i < D * D; i += 128) {
        int o = i / D, k = i % D;
        ws[k * WS + o] = Wr[i];
    }
    __syncthreads();

    if (active) {
#pragma unroll 1
        for (int kb = 0; kb < D / 4; kb++) {
            float4 fv = f4[kb];
            const ulonglong2* w0 = (const ulonglong2*)(ws + (4 * kb + 0) * WS + obase);
            const ulonglong2* w1 = (const ulonglong2*)(ws + (4 * kb + 1) * WS + obase);
            const ulonglong2* w2 = (const ulonglong2*)(ws + (4 * kb + 2) * WS + obase);
            const ulonglong2* w3 = (const ulonglong2*)(ws + (4 * kb + 3) * WS + obase);
            u64 ax = pack2(fv.x, fv.x);
            u64 ay = pack2(fv.y, fv.y);
            u64 az = pack2(fv.z, fv.z);
            u64 aw = pack2(fv.w, fv.w);
#pragma unroll
            for (int j = 0; j < 6; j++) {
                ulonglong2 w = w0[j];
                fma2(acc[2 * j], ax, w.x); fma2(acc[2 * j + 1], ax, w.y);
            }
#pragma unroll
            for (int j = 0; j < 6; j++) {
                ulonglong2 w = w1[j];
                fma2(acc[2 * j], ay, w.x); fma2(acc[2 * j + 1], ay, w.y);
            }
#pragma unroll
            for (int j = 0; j < 6; j++) {
                ulonglong2 w = w2[j];
                fma2(acc[2 * j], az, w.x); fma2(acc[2 * j + 1], az, w.y);
            }
#pragma unroll
            for (int j = 0; j < 6; j++) {
                ulonglong2 w = w3[j];
                fma2(acc[2 * j], aw, w.x); fma2(acc[2 * j + 1], aw, w.y);
            }
        }

        float* o = dst + (size_t)node * D + obase;
        float4* o4 = (float4*)o;
#pragma unroll
        for (int j = 0; j < 6; j++) {
            float v0, v1, v2, v3;
            unpack2(acc[2 * j],     v0, v1);
            unpack2(acc[2 * j + 1], v2, v3);
            if (apply_elu) {
                v0 = v0 > 0.0f ? v0 : expm1f(v0);
                v1 = v1 > 0.0f ? v1 : expm1f(v1);
                v2 = v2 > 0.0f ? v2 : expm1f(v2);
                v3 = v3 > 0.0f ? v3 : expm1f(v3);
            }
            o4[j] = make_float4(v0, v1, v2, v3);
        }
    }
}

// ---------------------------------------------------------------------------
// Launch sequence (graph-capturable; kernel launches only).
// ---------------------------------------------------------------------------
extern "C" void kernel_launch(void* const* d_in, const int* in_sizes, int n_in,
                              void* d_out, int out_size) {
    const float* x   = (const float*)d_in[0];
    const void*  ei  = d_in[1];
    const float* W1l = (const float*)d_in[2];
    const float* b1  = (const float*)d_in[3];
    const float* W1r = (const float*)d_in[4];
    const float* W2l = (const float*)d_in[5];
    const float* b2  = (const float*)d_in[6];
    const float* W2r = (const float*)d_in[7];
    float*       out = (float*)d_out;

    const int nb = (N_NODES + 255) / 256;
    const int hb = (N_EDGES / 4 + 255) / 256;
    const int pb = (N_EDGES / 2 + 255) / 256;
    const int wb = (N_NODES * 32 + 255) / 256;
    const int gb = (N_NODES + 31) / 32;          // 4 threads/node, 128/block

    // CSR build (shared by both layers)
    zero_detect_kernel<<<nb, 256>>>((const int*)ei);   // 1
    hist_kernel<<<hb, 256>>>(ei);                       // 2
    scan_kernel<<<SCAN_B, SCAN_T>>>();                  // 3
    place_kernel<<<pb, 256>>>(ei);                      // 4

    // Layer 1
    gather_kernel<<<wb, 256>>>(x, 0);                   // 5
    gemm_kernel<<<gb, 128>>>(x, 0, W1l, W1r, b1, nullptr, 1, 1);   // 6

    // Layer 2
    gather_kernel<<<wb, 256>>>(nullptr, 1);             // 7
    gemm_kernel<<<gb, 128>>>(nullptr, 1, W2l, W2r, b2, out, 0, 0); // 8
}

// round 12
// speedup vs baseline: 1.3209x; 1.3209x over previous
#include <cuda_runtime.h>

#define N_NODES 50000
#define N_EDGES 800000
#define D 96
#define WS 100                  // padded weight stride (floats)
#define SCAN_T 1024
#define SCAN_B ((N_NODES + SCAN_T - 1) / SCAN_T)   // 49

typedef unsigned long long u64;

__device__ __align__(16) float g_agg[N_NODES * D];   // gathered mean features
__device__ __align__(16) float g_h[N_NODES * D];     // layer-1 activations
__device__ int g_deg[N_NODES];
__device__ int g_off[N_NODES + 1];
__device__ int g_cur[N_NODES];                        // placement cursors (seeded)
__device__ int g_src[N_EDGES];                        // CSR: src ids grouped by dst
__device__ int g_part[SCAN_B];
__device__ int g_flag[SCAN_B];
__device__ int g_is64;

__device__ __forceinline__ u64 pack2(float lo, float hi) {
    u64 r; asm("mov.b64 %0, {%1, %2};" : "=l"(r) : "f"(lo), "f"(hi)); return r;
}
__device__ __forceinline__ void unpack2(u64 v, float& lo, float& hi) {
    asm("mov.b64 {%0, %1}, %2;" : "=f"(lo), "=f"(hi) : "l"(v));
}
__device__ __forceinline__ void fma2(u64& d, u64 a, u64 b) {
    asm("fma.rn.f32x2 %0, %1, %2, %0;" : "+l"(d) : "l"(a), "l"(b));
}
__device__ __forceinline__ int clampi(int v) {
    return min(max(v, 0), N_NODES - 1);
}

// ---------------------------------------------------------------------------
// Zero degrees + flags; block 0 detects edge_index element width.
// ---------------------------------------------------------------------------
__global__ void zero_detect_kernel(const int* __restrict__ w) {
    int i = blockIdx.x * blockDim.x + threadIdx.x;
    if (i < N_NODES) g_deg[i] = 0;
    if (i < SCAN_B) g_flag[i] = 0;
    if (blockIdx.x == 0 && threadIdx.x < 64) {
        int t = threadIdx.x;
        int bad = (w[2 * t + 1] != 0) ? 1 : 0;
        unsigned m0 = __ballot_sync(0xffffffffu, bad);
        __shared__ unsigned s[2];
        s[t >> 5] = m0;
        __syncwarp();
        if (t == 0) {
            __threadfence_block();
            g_is64 = (s[0] | s[1]) ? 0 : 1;
        }
    }
}

__device__ __forceinline__ int load_idx(const void* eiv, int pos) {
    int v;
    if (g_is64) v = (int)((const long long*)eiv)[pos];
    else        v = ((const int*)eiv)[pos];
    return clampi(v);
}

// hist: 4 edges per thread, vector index loads
__global__ void hist_kernel(const void* __restrict__ eiv) {
    int e = 4 * (blockIdx.x * blockDim.x + threadIdx.x);
    if (e + 3 < N_EDGES) {
        int d0, d1, d2, d3;
        if (g_is64) {
            const longlong2* p = (const longlong2*)((const long long*)eiv + N_EDGES + e);
            longlong2 a = p[0], b = p[1];
            d0 = (int)a.x; d1 = (int)a.y; d2 = (int)b.x; d3 = (int)b.y;
        } else {
            int4 a = *(const int4*)((const int*)eiv + N_EDGES + e);
            d0 = a.x; d1 = a.y; d2 = a.z; d3 = a.w;
        }
        atomicAdd(&g_deg[clampi(d0)], 1);
        atomicAdd(&g_deg[clampi(d1)], 1);
        atomicAdd(&g_deg[clampi(d2)], 1);
        atomicAdd(&g_deg[clampi(d3)], 1);
    } else {
        for (int k = e; k < N_EDGES; k++)
            atomicAdd(&g_deg[load_idx(eiv, N_EDGES + k)], 1);
    }
}

// ---------------------------------------------------------------------------
// Single-pass scan with decoupled lookback; seeds g_cur with offsets.
// ---------------------------------------------------------------------------
__global__ __launch_bounds__(SCAN_T) void scan_kernel() {
    __shared__ int wsum[32];
    __shared__ int red[2];
    __shared__ int sbase;

    int tid = threadIdx.x;
    int bx  = blockIdx.x;
    int i = bx * SCAN_T + tid;
    int v = (i < N_NODES) ? g_deg[i] : 0;

    int s = v;
#pragma unroll
    for (int o = 1; o < 32; o <<= 1) {
        int u = __shfl_up_sync(0xffffffffu, s, o);
        if ((tid & 31) >= o) s += u;
    }
    if ((tid & 31) == 31) wsum[tid >> 5] = s;
    __syncthreads();
    if (tid < 32) {
        int t = wsum[tid];
#pragma unroll
        for (int o = 1; o < 32; o <<= 1) {
            int u = __shfl_up_sync(0xffffffffu, t, o);
            if (tid >= o) t += u;
        }
        wsum[tid] = t;
    }
    __syncthreads();

    if (tid == 0) {
        g_part[bx] = wsum[31];
        __threadfence();
        ((volatile int*)g_flag)[bx] = 1;
    }

    if (tid < 64) {
        int val = 0;
        if (tid < bx) {
            while (((volatile int*)g_flag)[tid] == 0) {}
            __threadfence();
            val = ((volatile int*)g_part)[tid];
        }
#pragma unroll
        for (int o = 16; o > 0; o >>= 1)
            val += __shfl_xor_sync(0xffffffffu, val, o);
        if ((tid & 31) == 0) red[tid >> 5] = val;
    }
    __syncthreads();
    if (tid == 0) sbase = red[0] + red[1];
    __syncthreads();

    int warp = tid >> 5;
    int wbase = warp ? wsum[warp - 1] : 0;
    int excl = sbase + wbase + (s - v);
    if (i < N_NODES) {
        g_off[i] = excl;
        g_cur[i] = excl;
        if (i == N_NODES - 1) g_off[N_NODES] = excl + v;
    }
}

// place: 2 edges per thread, paired index loads; atomic on seeded cursor
__global__ void place_kernel(const void* __restrict__ eiv) {
    int e = 2 * (blockIdx.x * blockDim.x + threadIdx.x);
    if (e + 1 < N_EDGES) {
        int s0, s1, d0, d1;
        if (g_is64) {
            longlong2 sp = *(const longlong2*)((const long long*)eiv + e);
            longlong2 dp = *(const longlong2*)((const long long*)eiv + N_EDGES + e);
            s0 = (int)sp.x; s1 = (int)sp.y; d0 = (int)dp.x; d1 = (int)dp.y;
        } else {
            int2 sp = *(const int2*)((const int*)eiv + e);
            int2 dp = *(const int2*)((const int*)eiv + N_EDGES + e);
            s0 = sp.x; s1 = sp.y; d0 = dp.x; d1 = dp.y;
        }
        s0 = clampi(s0); s1 = clampi(s1);
        int p0 = atomicAdd(&g_cur[clampi(d0)], 1);
        int p1 = atomicAdd(&g_cur[clampi(d1)], 1);
        if (p0 >= 0 && p0 < N_EDGES) g_src[p0] = s0;
        if (p1 >= 0 && p1 < N_EDGES) g_src[p1] = s1;
    } else if (e < N_EDGES) {
        int src = load_idx(eiv, e);
        int dst = load_idx(eiv, N_EDGES + e);
        int pos = atomicAdd(&g_cur[dst], 1);
        if (pos >= 0 && pos < N_EDGES) g_src[pos] = src;
    }
}

// ---------------------------------------------------------------------------
// Gather mean: one warp per node; 24 active lanes, one float4 per lane per
// edge. 8-edge unroll to hide L2 latency.
// ---------------------------------------------------------------------------
__global__ __launch_bounds__(256) void gather_kernel(const float* __restrict__ x,
                                                     int from_h) {
    int warp = (blockIdx.x * blockDim.x + threadIdx.x) >> 5;
    int lane = threadIdx.x & 31;
    if (warp >= N_NODES) return;
    const float* feat = from_h ? (const float*)g_h : x;
    int beg = g_off[warp];
    int end = g_off[warp + 1];
    bool act = lane < 24;
    float4 a = make_float4(0.f, 0.f, 0.f, 0.f);
    float4 b = make_float4(0.f, 0.f, 0.f, 0.f);
    int i = beg;
    for (; i + 7 < end; i += 8) {
        int s0 = g_src[i],     s1 = g_src[i + 1], s2 = g_src[i + 2], s3 = g_src[i + 3];
        int s4 = g_src[i + 4], s5 = g_src[i + 5], s6 = g_src[i + 6], s7 = g_src[i + 7];
        if (act) {
            float4 v0 = ((const float4*)(feat + (size_t)s0 * D))[lane];
            float4 v1 = ((const float4*)(feat + (size_t)s1 * D))[lane];
            float4 v2 = ((const float4*)(feat + (size_t)s2 * D))[lane];
            float4 v3 = ((const float4*)(feat + (size_t)s3 * D))[lane];
            float4 v4 = ((const float4*)(feat + (size_t)s4 * D))[lane];
            float4 v5 = ((const float4*)(feat + (size_t)s5 * D))[lane];
            float4 v6 = ((const float4*)(feat + (size_t)s6 * D))[lane];
            float4 v7 = ((const float4*)(feat + (size_t)s7 * D))[lane];
            a.x += (v0.x + v1.x) + (v2.x + v3.x);
            a.y += (v0.y + v1.y) + (v2.y + v3.y);
            a.z += (v0.z + v1.z) + (v2.z + v3.z);
            a.w += (v0.w + v1.w) + (v2.w + v3.w);
            b.x += (v4.x + v5.x) + (v6.x + v7.x);
            b.y += (v4.y + v5.y) + (v6.y + v7.y);
            b.z += (v4.z + v5.z) + (v6.z + v7.z);
            b.w += (v4.w + v5.w) + (v6.w + v7.w);
        }
    }
    for (; i + 1 < end; i += 2) {
        int s0 = g_src[i], s1 = g_src[i + 1];
        if (act) {
            float4 v0 = ((const float4*)(feat + (size_t)s0 * D))[lane];
            float4 v1 = ((const float4*)(feat + (size_t)s1 * D))[lane];
            a.x += v0.x + v1.x; a.y += v0.y + v1.y;
            a.z += v0.z + v1.z; a.w += v0.w + v1.w;
        }
    }
    if (i < end) {
        int s0 = g_src[i];
        if (act) {
            float4 v0 = ((const float4*)(feat + (size_t)s0 * D))[lane];
            a.x += v0.x; a.y += v0.y; a.z += v0.z; a.w += v0.w;
        }
    }
    if (act) {
        float inv = 1.0f / (float)max(end - beg, 1);
        float4 r;
        r.x = (a.x + b.x) * inv;
        r.y = (a.y + b.y) * inv;
        r.z = (a.z + b.z) * inv;
        r.w = (a.w + b.w) * inv;
        ((float4*)(g_agg + (size_t)warp * D))[lane] = r;
    }
}

// ---------------------------------------------------------------------------
// Fused SAGE linear layer, 2 threads per node, 256-thread blocks
// (128 nodes/block): halves weight-staging traffic vs 128-thread blocks and
// the whole grid (391 blocks) is fully resident in one wave.
// ---------------------------------------------------------------------------
__global__ __launch_bounds__(256) void gemm_kernel(
    const float* __restrict__ x, int in_h,
    const float* __restrict__ Wl,
    const float* __restrict__ Wr,
    const float* __restrict__ bias,
    float* __restrict__ out, int out_h,
    int apply_elu)
{
    __shared__ __align__(16) float ws[D * WS];   // ws[k*WS + o] = W[o][k]
    __shared__ float bsm[D];

    const float* feat = in_h ? (const float*)g_h : x;
    float* dst = out_h ? (float*)g_h : out;

    for (int i = threadIdx.x; i < D * D; i += 256) {
        int o = i / D, k = i % D;
        ws[k * WS + o] = Wl[i];
    }
    if (threadIdx.x < D) bsm[threadIdx.x] = bias[threadIdx.x];
    __syncthreads();

    int node = blockIdx.x * 128 + (threadIdx.x >> 1);
    int obase = (threadIdx.x & 1) * 48;          // this thread's output half
    bool active = node < N_NODES;

    u64 acc[24];
#pragma unroll
    for (int j = 0; j < 24; j++)
        acc[j] = pack2(bsm[obase + 2 * j], bsm[obase + 2 * j + 1]);

    const float4* a4 = (const float4*)(g_agg + (size_t)node * D);
    const float4* f4 = (const float4*)(feat + (size_t)node * D);

    if (active) {
#pragma unroll 1
        for (int kb = 0; kb < D / 4; kb++) {
            float4 av = a4[kb];
            const ulonglong2* w0 = (const ulonglong2*)(ws + (4 * kb + 0) * WS + obase);
            const ulonglong2* w1 = (const ulonglong2*)(ws + (4 * kb + 1) * WS + obase);
            const ulonglong2* w2 = (const ulonglong2*)(ws + (4 * kb + 2) * WS + obase);
            const ulonglong2* w3 = (const ulonglong2*)(ws + (4 * kb + 3) * WS + obase);
            u64 ax = pack2(av.x, av.x);
            u64 ay = pack2(av.y, av.y);
            u64 az = pack2(av.z, av.z);
            u64 aw = pack2(av.w, av.w);
#pragma unroll
            for (int j = 0; j < 12; j++) {
                ulonglong2 w = w0[j];
                fma2(acc[2 * j], ax, w.x); fma2(acc[2 * j + 1], ax, w.y);
            }
#pragma unroll
            for (int j = 0; j < 12; j++) {
                ulonglong2 w = w1[j];
                fma2(acc[2 * j], ay, w.x); fma2(acc[2 * j + 1], ay, w.y);
            }
#pragma unroll
            for (int j = 0; j < 12; j++) {
                ulonglong2 w = w2[j];
                fma2(acc[2 * j], az, w.x); fma2(acc[2 * j + 1], az, w.y);
            }
#pragma unroll
            for (int j = 0; j < 12; j++) {
                ulonglong2 w = w3[j];
                fma2(acc[2 * j], aw, w.x); fma2(acc[2 * j + 1], aw, w.y);
            }
        }
    }

    __syncthreads();
    for (int i = threadIdx.x; i < D * D; i += 256) {
        int o = i / D, k = i % D;
        ws[k * WS + o] = Wr[i];
    }
    __syncthreads();

    if (active) {
#pragma unroll 1
        for (int kb = 0; kb < D / 4; kb++) {
            float4 fv = f4[kb];
            const ulonglong2* w0 = (const ulonglong2*)(ws + (4 * kb + 0) * WS + obase);
            const ulonglong2* w1 = (const ulonglong2*)(ws + (4 * kb + 1) * WS + obase);
            const ulonglong2* w2 = (const ulonglong2*)(ws + (4 * kb + 2) * WS + obase);
            const ulonglong2* w3 = (const ulonglong2*)(ws + (4 * kb + 3) * WS + obase);
            u64 ax = pack2(fv.x, fv.x);
            u64 ay = pack2(fv.y, fv.y);
            u64 az = pack2(fv.z, fv.z);
            u64 aw = pack2(fv.w, fv.w);
#pragma unroll
            for (int j = 0; j < 12; j++) {
                ulonglong2 w = w0[j];
                fma2(acc[2 * j], ax, w.x); fma2(acc[2 * j + 1], ax, w.y);
            }
#pragma unroll
            for (int j = 0; j < 12; j++) {
                ulonglong2 w = w1[j];
                fma2(acc[2 * j], ay, w.x); fma2(acc[2 * j + 1], ay, w.y);
            }
#pragma unroll
            for (int j = 0; j < 12; j++) {
                ulonglong2 w = w2[j];
                fma2(acc[2 * j], az, w.x); fma2(acc[2 * j + 1], az, w.y);
            }
#pragma unroll
            for (int j = 0; j < 12; j++) {
                ulonglong2 w = w3[j];
                fma2(acc[2 * j], aw, w.x); fma2(acc[2 * j + 1], aw, w.y);
            }
        }

        float* o = dst + (size_t)node * D + obase;
        float4* o4 = (float4*)o;
#pragma unroll
        for (int j = 0; j < 12; j++) {
            float v0, v1, v2, v3;
            unpack2(acc[2 * j],     v0, v1);
            unpack2(acc[2 * j + 1], v2, v3);
            if (apply_elu) {
                v0 = v0 > 0.0f ? v0 : expm1f(v0);
                v1 = v1 > 0.0f ? v1 : expm1f(v1);
                v2 = v2 > 0.0f ? v2 : expm1f(v2);
                v3 = v3 > 0.0f ? v3 : expm1f(v3);
            }
            o4[j] = make_float4(v0, v1, v2, v3);
        }
    }
}

// ---------------------------------------------------------------------------
// Launch sequence (graph-capturable; kernel launches only).
// ---------------------------------------------------------------------------
extern "C" void kernel_launch(void* const* d_in, const int* in_sizes, int n_in,
                              void* d_out, int out_size) {
    const float* x   = (const float*)d_in[0];
    const void*  ei  = d_in[1];
    const float* W1l = (const float*)d_in[2];
    const float* b1  = (const float*)d_in[3];
    const float* W1r = (const float*)d_in[4];
    const float* W2l = (const float*)d_in[5];
    const float* b2  = (const float*)d_in[6];
    const float* W2r = (const float*)d_in[7];
    float*       out = (float*)d_out;

    const int nb = (N_NODES + 255) / 256;
    const int hb = (N_EDGES / 4 + 255) / 256;
    const int pb = (N_EDGES / 2 + 255) / 256;
    const int wb = (N_NODES * 32 + 255) / 256;
    const int gb = (N_NODES + 127) / 128;        // 2 threads/node, 256/block

    // CSR build (shared by both layers)
    zero_detect_kernel<<<nb, 256>>>((const int*)ei);   // 1
    hist_kernel<<<hb, 256>>>(ei);                       // 2
    scan_kernel<<<SCAN_B, SCAN_T>>>();                  // 3
    place_kernel<<<pb, 256>>>(ei);                      // 4

    // Layer 1
    gather_kernel<<<wb, 256>>>(x, 0);                   // 5
    gemm_kernel<<<gb, 256>>>(x, 0, W1l, W1r, b1, nullptr, 1, 1);   // 6

    // Layer 2
    gather_kernel<<<wb, 256>>>(nullptr, 1);             // 7
    gemm_kernel<<<gb, 256>>>(nullptr, 1, W2l, W2r, b2, out, 0, 0); // 8
}

// round 13
// speedup vs baseline: 1.3875x; 1.0504x over previous
#include <cuda_runtime.h>

#define N_NODES 50000
#define N_EDGES 800000
#define D 96
#define WS 100                  // padded weight stride (floats)
#define SCAN_T 1024
#define SCAN_B ((N_NODES + SCAN_T - 1) / SCAN_T)   // 49

typedef unsigned long long u64;

__device__ __align__(16) float g_agg[N_NODES * D];   // gathered mean features
__device__ __align__(16) float g_h[N_NODES * D];     // layer-1 activations
__device__ int g_deg[N_NODES];     // INVARIANT: all-zero at kernel_launch entry
__device__ int g_off[N_NODES + 1];
__device__ int g_cur[N_NODES];                        // placement cursors (seeded)
__device__ int g_src[N_EDGES];                        // CSR: src ids grouped by dst
__device__ int g_part[SCAN_B];
__device__ int g_flag[SCAN_B];     // INVARIANT: all-zero at entry (place clears)

__device__ __forceinline__ u64 pack2(float lo, float hi) {
    u64 r; asm("mov.b64 %0, {%1, %2};" : "=l"(r) : "f"(lo), "f"(hi)); return r;
}
__device__ __forceinline__ void unpack2(u64 v, float& lo, float& hi) {
    asm("mov.b64 {%0, %1}, %2;" : "=f"(lo), "=f"(hi) : "l"(v));
}
__device__ __forceinline__ void fma2(u64& d, u64 a, u64 b) {
    asm("fma.rn.f32x2 %0, %1, %2, %0;" : "+l"(d) : "l"(a), "l"(b));
}
__device__ __forceinline__ int clampi(int v) {
    return min(max(v, 0), N_NODES - 1);
}

// Per-block edge-width detect: int64 small non-negative ids => odd 32-bit
// words of the first 128 words are all zero. Result broadcast via shared.
__device__ __forceinline__ int block_detect_is64(const int* __restrict__ w) {
    __shared__ int s_is64;
    if (threadIdx.x < 64) {
        int bad = (w[2 * threadIdx.x + 1] != 0) ? 1 : 0;
        unsigned m = __ballot_sync(0xffffffffu, bad);
        __shared__ unsigned sm[2];
        sm[threadIdx.x >> 5] = m;
        __syncwarp();
        if (threadIdx.x == 0) s_is64 = (sm[0] | sm[1]) ? 0 : 1;
    }
    __syncthreads();
    return s_is64;
}

// ---------------------------------------------------------------------------
// hist: 4 edges per thread, vector index loads. g_deg pre-zeroed by invariant.
// ---------------------------------------------------------------------------
__global__ void hist_kernel(const void* __restrict__ eiv) {
    int is64 = block_detect_is64((const int*)eiv);
    int e = 4 * (blockIdx.x * blockDim.x + threadIdx.x);
    if (e + 3 < N_EDGES) {
        int d0, d1, d2, d3;
        if (is64) {
            const longlong2* p = (const longlong2*)((const long long*)eiv + N_EDGES + e);
            longlong2 a = p[0], b = p[1];
            d0 = (int)a.x; d1 = (int)a.y; d2 = (int)b.x; d3 = (int)b.y;
        } else {
            int4 a = *(const int4*)((const int*)eiv + N_EDGES + e);
            d0 = a.x; d1 = a.y; d2 = a.z; d3 = a.w;
        }
        atomicAdd(&g_deg[clampi(d0)], 1);
        atomicAdd(&g_deg[clampi(d1)], 1);
        atomicAdd(&g_deg[clampi(d2)], 1);
        atomicAdd(&g_deg[clampi(d3)], 1);
    } else {
        for (int k = e; k < N_EDGES; k++) {
            int d;
            if (is64) d = (int)((const long long*)eiv)[N_EDGES + k];
            else      d = ((const int*)eiv)[N_EDGES + k];
            atomicAdd(&g_deg[clampi(d)], 1);
        }
    }
}

// ---------------------------------------------------------------------------
// Single-pass scan with decoupled lookback; seeds g_cur; re-zeros g_deg to
// restore the entry invariant for the next call.
// ---------------------------------------------------------------------------
__global__ __launch_bounds__(SCAN_T) void scan_kernel() {
    __shared__ int wsum[32];
    __shared__ int red[2];
    __shared__ int sbase;

    int tid = threadIdx.x;
    int bx  = blockIdx.x;
    int i = bx * SCAN_T + tid;
    int v = (i < N_NODES) ? g_deg[i] : 0;
    if (i < N_NODES) g_deg[i] = 0;           // restore invariant

    int s = v;
#pragma unroll
    for (int o = 1; o < 32; o <<= 1) {
        int u = __shfl_up_sync(0xffffffffu, s, o);
        if ((tid & 31) >= o) s += u;
    }
    if ((tid & 31) == 31) wsum[tid >> 5] = s;
    __syncthreads();
    if (tid < 32) {
        int t = wsum[tid];
#pragma unroll
        for (int o = 1; o < 32; o <<= 1) {
            int u = __shfl_up_sync(0xffffffffu, t, o);
            if (tid >= o) t += u;
        }
        wsum[tid] = t;
    }
    __syncthreads();

    if (tid == 0) {
        g_part[bx] = wsum[31];
        __threadfence();
        ((volatile int*)g_flag)[bx] = 1;
    }

    if (tid < 64) {
        int val = 0;
        if (tid < bx) {
            while (((volatile int*)g_flag)[tid] == 0) {}
            __threadfence();
            val = ((volatile int*)g_part)[tid];
        }
#pragma unroll
        for (int o = 16; o > 0; o >>= 1)
            val += __shfl_xor_sync(0xffffffffu, val, o);
        if ((tid & 31) == 0) red[tid >> 5] = val;
    }
    __syncthreads();
    if (tid == 0) sbase = red[0] + red[1];
    __syncthreads();

    int warp = tid >> 5;
    int wbase = warp ? wsum[warp - 1] : 0;
    int excl = sbase + wbase + (s - v);
    if (i < N_NODES) {
        g_off[i] = excl;
        g_cur[i] = excl;
        if (i == N_NODES - 1) g_off[N_NODES] = excl + v;
    }
}

// ---------------------------------------------------------------------------
// place: 2 edges per thread; atomic on seeded cursor. Clears g_flag for the
// next call (restores invariant).
// ---------------------------------------------------------------------------
__global__ void place_kernel(const void* __restrict__ eiv) {
    int is64 = block_detect_is64((const int*)eiv);
    int gid = blockIdx.x * blockDim.x + threadIdx.x;
    if (gid < SCAN_B) g_flag[gid] = 0;       // restore invariant
    int e = 2 * gid;
    if (e + 1 < N_EDGES) {
        int s0, s1, d0, d1;
        if (is64) {
            longlong2 sp = *(const longlong2*)((const long long*)eiv + e);
            longlong2 dp = *(const longlong2*)((const long long*)eiv + N_EDGES + e);
            s0 = (int)sp.x; s1 = (int)sp.y; d0 = (int)dp.x; d1 = (int)dp.y;
        } else {
            int2 sp = *(const int2*)((const int*)eiv + e);
            int2 dp = *(const int2*)((const int*)eiv + N_EDGES + e);
            s0 = sp.x; s1 = sp.y; d0 = dp.x; d1 = dp.y;
        }
        s0 = clampi(s0); s1 = clampi(s1);
        int p0 = atomicAdd(&g_cur[clampi(d0)], 1);
        int p1 = atomicAdd(&g_cur[clampi(d1)], 1);
        if (p0 >= 0 && p0 < N_EDGES) g_src[p0] = s0;
        if (p1 >= 0 && p1 < N_EDGES) g_src[p1] = s1;
    } else if (e < N_EDGES) {
        int src, dst;
        if (is64) {
            src = (int)((const long long*)eiv)[e];
            dst = (int)((const long long*)eiv)[N_EDGES + e];
        } else {
            src = ((const int*)eiv)[e];
            dst = ((const int*)eiv)[N_EDGES + e];
        }
        int pos = atomicAdd(&g_cur[clampi(dst)], 1);
        if (pos >= 0 && pos < N_EDGES) g_src[pos] = clampi(src);
    }
}

// ---------------------------------------------------------------------------
// Gather mean: one warp per node; 24 active lanes, one float4 per lane per
// edge. 8-edge unroll to hide L2 latency.
// ---------------------------------------------------------------------------
__global__ __launch_bounds__(256) void gather_kernel(const float* __restrict__ x,
                                                     int from_h) {
    int warp = (blockIdx.x * blockDim.x + threadIdx.x) >> 5;
    int lane = threadIdx.x & 31;
    if (warp >= N_NODES) return;
    const float* feat = from_h ? (const float*)g_h : x;
    int beg = g_off[warp];
    int end = g_off[warp + 1];
    bool act = lane < 24;
    float4 a = make_float4(0.f, 0.f, 0.f, 0.f);
    float4 b = make_float4(0.f, 0.f, 0.f, 0.f);
    int i = beg;
    for (; i + 7 < end; i += 8) {
        int s0 = g_src[i],     s1 = g_src[i + 1], s2 = g_src[i + 2], s3 = g_src[i + 3];
        int s4 = g_src[i + 4], s5 = g_src[i + 5], s6 = g_src[i + 6], s7 = g_src[i + 7];
        if (act) {
            float4 v0 = ((const float4*)(feat + (size_t)s0 * D))[lane];
            float4 v1 = ((const float4*)(feat + (size_t)s1 * D))[lane];
            float4 v2 = ((const float4*)(feat + (size_t)s2 * D))[lane];
            float4 v3 = ((const float4*)(feat + (size_t)s3 * D))[lane];
            float4 v4 = ((const float4*)(feat + (size_t)s4 * D))[lane];
            float4 v5 = ((const float4*)(feat + (size_t)s5 * D))[lane];
            float4 v6 = ((const float4*)(feat + (size_t)s6 * D))[lane];
            float4 v7 = ((const float4*)(feat + (size_t)s7 * D))[lane];
            a.x += (v0.x + v1.x) + (v2.x + v3.x);
            a.y += (v0.y + v1.y) + (v2.y + v3.y);
            a.z += (v0.z + v1.z) + (v2.z + v3.z);
            a.w += (v0.w + v1.w) + (v2.w + v3.w);
            b.x += (v4.x + v5.x) + (v6.x + v7.x);
            b.y += (v4.y + v5.y) + (v6.y + v7.y);
            b.z += (v4.z + v5.z) + (v6.z + v7.z);
            b.w += (v4.w + v5.w) + (v6.w + v7.w);
        }
    }
    for (; i + 1 < end; i += 2) {
        int s0 = g_src[i], s1 = g_src[i + 1];
        if (act) {
            float4 v0 = ((const float4*)(feat + (size_t)s0 * D))[lane];
            float4 v1 = ((const float4*)(feat + (size_t)s1 * D))[lane];
            a.x += v0.x + v1.x; a.y += v0.y + v1.y;
            a.z += v0.z + v1.z; a.w += v0.w + v1.w;
        }
    }
    if (i < end) {
        int s0 = g_src[i];
        if (act) {
            float4 v0 = ((const float4*)(feat + (size_t)s0 * D))[lane];
            a.x += v0.x; a.y += v0.y; a.z += v0.z; a.w += v0.w;
        }
    }
    if (act) {
        float inv = 1.0f / (float)max(end - beg, 1);
        float4 r;
        r.x = (a.x + b.x) * inv;
        r.y = (a.y + b.y) * inv;
        r.z = (a.z + b.z) * inv;
        r.w = (a.w + b.w) * inv;
        ((float4*)(g_agg + (size_t)warp * D))[lane] = r;
    }
}

// ---------------------------------------------------------------------------
// Fused SAGE linear layer (R10-proven shape): 2 threads/node, 128-thread
// blocks, 24 packed f32x2 accumulators, LDS.128 weight reads.
// ---------------------------------------------------------------------------
__global__ __launch_bounds__(128) void gemm_kernel(
    const float* __restrict__ x, int in_h,
    const float* __restrict__ Wl,
    const float* __restrict__ Wr,
    const float* __restrict__ bias,
    float* __restrict__ out, int out_h,
    int apply_elu)
{
    __shared__ __align__(16) float ws[D * WS];   // ws[k*WS + o] = W[o][k]
    __shared__ float bsm[D];

    const float* feat = in_h ? (const float*)g_h : x;
    float* dst = out_h ? (float*)g_h : out;

    for (int i = threadIdx.x; i < D * D; i += 128) {
        int o = i / D, k = i % D;
        ws[k * WS + o] = Wl[i];
    }
    if (threadIdx.x < D) bsm[threadIdx.x] = bias[threadIdx.x];
    __syncthreads();

    int node = blockIdx.x * 64 + (threadIdx.x >> 1);
    int obase = (threadIdx.x & 1) * 48;          // this thread's output half
    bool active = node < N_NODES;

    u64 acc[24];
#pragma unroll
    for (int j = 0; j < 24; j++)
        acc[j] = pack2(bsm[obase + 2 * j], bsm[obase + 2 * j + 1]);

    const float4* a4 = (const float4*)(g_agg + (size_t)node * D);
    const float4* f4 = (const float4*)(feat + (size_t)node * D);

    if (active) {
#pragma unroll 1
        for (int kb = 0; kb < D / 4; kb++) {
            float4 av = a4[kb];
            const ulonglong2* w0 = (const ulonglong2*)(ws + (4 * kb + 0) * WS + obase);
            const ulonglong2* w1 = (const ulonglong2*)(ws + (4 * kb + 1) * WS + obase);
            const ulonglong2* w2 = (const ulonglong2*)(ws + (4 * kb + 2) * WS + obase);
            const ulonglong2* w3 = (const ulonglong2*)(ws + (4 * kb + 3) * WS + obase);
            u64 ax = pack2(av.x, av.x);
            u64 ay = pack2(av.y, av.y);
            u64 az = pack2(av.z, av.z);
            u64 aw = pack2(av.w, av.w);
#pragma unroll
            for (int j = 0; j < 12; j++) {
                ulonglong2 w = w0[j];
                fma2(acc[2 * j], ax, w.x); fma2(acc[2 * j + 1], ax, w.y);
            }
#pragma unroll
            for (int j = 0; j < 12; j++) {
                ulonglong2 w = w1[j];
                fma2(acc[2 * j], ay, w.x); fma2(acc[2 * j + 1], ay, w.y);
            }
#pragma unroll
            for (int j = 0; j < 12; j++) {
                ulonglong2 w = w2[j];
                fma2(acc[2 * j], az, w.x); fma2(acc[2 * j + 1], az, w.y);
            }
#pragma unroll
            for (int j = 0; j < 12; j++) {
                ulonglong2 w = w3[j];
                fma2(acc[2 * j], aw, w.x); fma2(acc[2 * j + 1], aw, w.y);
            }
        }
    }

    __syncthreads();
    for (int i = threadIdx.x; i < D * D; i += 128) {
        int o = i / D, k = i % D;
        ws[k * WS + o] = Wr[i];
    }
    __syncthreads();

    if (active) {
#pragma unroll 1
        for (int kb = 0; kb < D / 4; kb++) {
            float4 fv = f4[kb];
            const ulonglong2* w0 = (const ulonglong2*)(ws + (4 * kb + 0) * WS + obase);
            const ulonglong2* w1 = (const ulonglong2*)(ws + (4 * kb + 1) * WS + obase);
            const ulonglong2* w2 = (const ulonglong2*)(ws + (4 * kb + 2) * WS + obase);
            const ulonglong2* w3 = (const ulonglong2*)(ws + (4 * kb + 3) * WS + obase);
            u64 ax = pack2(fv.x, fv.x);
            u64 ay = pack2(fv.y, fv.y);
            u64 az = pack2(fv.z, fv.z);
            u64 aw = pack2(fv.w, fv.w);
#pragma unroll
            for (int j = 0; j < 12; j++) {
                ulonglong2 w = w0[j];
                fma2(acc[2 * j], ax, w.x); fma2(acc[2 * j + 1], ax, w.y);
            }
#pragma unroll
            for (int j = 0; j < 12; j++) {
                ulonglong2 w = w1[j];
                fma2(acc[2 * j], ay, w.x); fma2(acc[2 * j + 1], ay, w.y);
            }
#pragma unroll
            for (int j = 0; j < 12; j++) {
                ulonglong2 w = w2[j];
                fma2(acc[2 * j], az, w.x); fma2(acc[2 * j + 1], az, w.y);
            }
#pragma unroll
            for (int j = 0; j < 12; j++) {
                ulonglong2 w = w3[j];
                fma2(acc[2 * j], aw, w.x); fma2(acc[2 * j + 1], aw, w.y);
            }
        }

        float* o = dst + (size_t)node * D + obase;
        float4* o4 = (float4*)o;
#pragma unroll
        for (int j = 0; j < 12; j++) {
            float v0, v1, v2, v3;
            unpack2(acc[2 * j],     v0, v1);
            unpack2(acc[2 * j + 1], v2, v3);
            if (apply_elu) {
                v0 = v0 > 0.0f ? v0 : expm1f(v0);
                v1 = v1 > 0.0f ? v1 : expm1f(v1);
                v2 = v2 > 0.0f ? v2 : expm1f(v2);
                v3 = v3 > 0.0f ? v3 : expm1f(v3);
            }
            o4[j] = make_float4(v0, v1, v2, v3);
        }
    }
}

// ---------------------------------------------------------------------------
// Launch sequence (graph-capturable; kernel launches only). 7 launches;
// gather1 sits at profile slot #4.
// ---------------------------------------------------------------------------
extern "C" void kernel_launch(void* const* d_in, const int* in_sizes, int n_in,
                              void* d_out, int out_size) {
    const float* x   = (const float*)d_in[0];
    const void*  ei  = d_in[1];
    const float* W1l = (const float*)d_in[2];
    const float* b1  = (const float*)d_in[3];
    const float* W1r = (const float*)d_in[4];
    const float* W2l = (const float*)d_in[5];
    const float* b2  = (const float*)d_in[6];
    const float* W2r = (const float*)d_in[7];
    float*       out = (float*)d_out;

    const int hb = (N_EDGES / 4 + 255) / 256;
    const int pb = (N_EDGES / 2 + 255) / 256;
    const int wb = (N_NODES * 32 + 255) / 256;
    const int gb = (N_NODES + 63) / 64;          // 2 threads/node, 128/block

    // CSR build (3 kernels; zero/flag invariants maintained by scan/place)
    hist_kernel<<<hb, 256>>>(ei);                       // 1
    scan_kernel<<<SCAN_B, SCAN_T>>>();                  // 2
    place_kernel<<<pb, 256>>>(ei);                      // 3

    // Layer 1
    gather_kernel<<<wb, 256>>>(x, 0);                   // 4 <- profile slot
    gemm_kernel<<<gb, 128>>>(x, 0, W1l, W1r, b1, nullptr, 1, 1);   // 5

    // Layer 2
    gather_kernel<<<wb, 256>>>(nullptr, 1);             // 6
    gemm_kernel<<<gb, 128>>>(nullptr, 1, W2l, W2r, b2, out, 0, 0); // 7
}